// round 15
// baseline (speedup 1.0000x reference)
#include <cuda_runtime.h>
#include <cuda_fp16.h>
#include <cstdint>

#define HW   48
#define NB   4
#define NCI  64
#define NCO  64
#define ND   9
#define NTILES 36        // 9216 / 256
#define SAI_STRIDE (NB * 2304 * 128)     // bytes per sub-aperture image

// ---------------- device scratch (no allocation allowed) -------------------
// unpadded SAI tensor: [sai(81)][b(4)][oh(48)][ow(48)][ci(64)] fp16  (95.6 MB)
__device__ __half g_x[(size_t)81 * NB * HW * HW * NCI];
__device__ __half g_w[81 * NCI * NCO];                       // [tap][ci][co]
__device__ float  g_conv[(size_t)ND * NB * NCO * HW * HW];   // 21.2 MB

__device__ __forceinline__ uint32_t smem_u32(const void* p) {
    uint32_t a;
    asm("{ .reg .u64 t; cvta.to.shared.u64 t, %1; cvt.u32.u64 %0, t; }"
        : "=r"(a) : "l"(p));
    return a;
}

// ---------------------------------------------------------------------------
// Kernel B: reorg x[b][ci][432][432] -> SAI fp16 [sai][b][oh][ow][ci]
// v3: v1's high-MLP 16-ci float staging + smem output stage so the final
// global writes are full 128B ci-chunks (warp emits 512B contiguous).
// ---------------------------------------------------------------------------
#define OST_PITCH 80                       // halves; banks (8*col+cp) conflict-free
#define REORG_SMEM (16 * 433 * 4 + 432 * OST_PITCH * 2)   // 27712 + 69120 = 96832
__global__ void __launch_bounds__(256) reorg_kernel(const float* __restrict__ x) {
    extern __shared__ char rsm[];
    float*  xs  = (float*)rsm;                       // [16][433]
    __half* ost = (__half*)(rsm + 16 * 433 * 4);     // [432][OST_PITCH]
    const int ih = blockIdx.x, b = blockIdx.y;
    const int sh = ih % 9, ohm = ih / 9;

    for (int c0 = 0; c0 < NCI; c0 += 16) {
        if (c0) __syncthreads();
        // phase 1: stage 16 input rows (coalesced, high MLP)
        for (int i = threadIdx.x; i < 16 * 432; i += 256) {
            int ci = i / 432, iw = i - ci * 432;
            xs[ci * 433 + iw] = x[((size_t)(b * NCI + c0 + ci) * 432 + ih) * 432 + iw];
        }
        __syncthreads();
        // phase 2: convert + transpose into output stage
        for (int i = threadIdx.x; i < 432 * 8; i += 256) {
            int cp = i & 7, col = i >> 3;            // col = sw*48 + owm
            int sw = col / 48, owm = col - sw * 48;
            int iw = owm * 9 + sw;
            __half h0 = __float2half(xs[(2 * cp) * 433 + iw]);
            __half h1 = __float2half(xs[(2 * cp + 1) * 433 + iw]);
            *(__half2*)(ost + col * OST_PITCH + c0 + 2 * cp) =
                __halves2half2(h0, h1);
        }
    }
    __syncthreads();
    // phase 3: flush — full 128B ci-chunks, contiguous across owm
    for (int i = threadIdx.x; i < 432 * 8; i += 256) {
        int c = i & 7, col = i >> 3;
        int sw = col / 48, owm = col - sw * 48;
        float4 v = *(const float4*)(ost + col * OST_PITCH + c * 8);
        size_t o = (((size_t)(sh * 9 + sw) * NB + b) * 2304
                    + (size_t)ohm * 48 + owm) * NCI + c * 8;
        *(float4*)(g_x + o) = v;
    }
}

// ---------------------------------------------------------------------------
// Kernel C: weight prep  w[co][ci][kh][kw] -> g_w[tap][ci][co] fp16
// ---------------------------------------------------------------------------
__global__ void wprep_kernel(const float* __restrict__ w) {
    int idx = blockIdx.x * 256 + threadIdx.x;
    if (idx >= 81 * NCI * NCO) return;
    int co = idx & 63, ci = (idx >> 6) & 63, tap = idx >> 12;
    g_w[idx] = __float2half(w[(size_t)co * 5184 + ci * 81 + tap]);
}

// ---------------------------------------------------------------------------
// Kernel D: HMMA implicit-GEMM conv (R13 version, verbatim).
// grid (9, 36), 256 thr (8 warps), 2 CTAs/SM.
// CTA tile D[M=256 spatial][N=64 co], 81 taps, K=64/tap.
// OOB handled by cp.async src_size=0 zero-fill.
// ---------------------------------------------------------------------------
#define CONV_SMEM (2 * 32768 + 2 * 8192)    // 81920 B
__global__ void __launch_bounds__(256, 2) conv_kernel() {
    extern __shared__ __align__(128) char dsm[];
    const uint32_t smA = smem_u32(dsm);
    const uint32_t smB = smA + 65536u;

    const int dIdx = blockIdx.x, tile = blockIdx.y;
    const int d = dIdx - 4;
    const int m = d < 0 ? -d : d;
    const bool flip = (d > 0);
    const int t = threadIdx.x, lane = t & 31, w = t >> 5;

    // ---- staging precompute: thread owns 8 A chunks (16B) + 2 B chunks ----
    int32_t  FA[8];
    uint64_t pack_oh = 0, pack_ow = 0;
    #pragma unroll
    for (int i = 0; i < 8; i++) {
        int r = (t >> 3) + 32 * i;
        int s = tile * 256 + r;
        int ow = s % 48, oh = (s / 48) % 48;
        FA[i] = s * 128 + (t & 7) * 16;
        pack_oh |= (uint64_t)oh << (8 * i);
        pack_ow |= (uint64_t)ow << (8 * i);
    }
    const uint32_t dstA0 = smA + (uint32_t)(t >> 3) * 128u
                         + (uint32_t)(((t & 7) ^ ((t >> 3) & 7)) << 4);
    const uint32_t dstB0 = smB + (uint32_t)(t >> 3) * 128u
                         + (uint32_t)(((t & 7) ^ ((t >> 3) & 7)) << 4);

    // ---- ldmatrix lane addresses ----
    uint32_t adA[2][4], adB0[4];
    #pragma unroll
    for (int j = 0; j < 2; j++)
        #pragma unroll
        for (int kc = 0; kc < 4; kc++) {
            int row = 32 * w + 16 * j + (lane & 15);
            int ch  = kc * 2 + (lane >> 4);
            adA[j][kc] = (uint32_t)(row * 128) + (uint32_t)((ch ^ (row & 7)) << 4);
        }
    #pragma unroll
    for (int q = 0; q < 4; q++) {
        int row = lane & 15;
        int ch  = q * 2 + (lane >> 4);
        adB0[q] = (uint32_t)(row * 128) + (uint32_t)((ch ^ (row & 7)) << 4);
    }

    float acc[2][8][4];
    #pragma unroll
    for (int j = 0; j < 2; j++)
        #pragma unroll
        for (int nt = 0; nt < 8; nt++)
            #pragma unroll
            for (int k = 0; k < 4; k++) acc[j][nt][k] = 0.f;

    const char* xb = (const char*)g_x;
    const char* wb = (const char*)g_w + (size_t)t * 16;

    auto stage = [&](int tap, uint32_t pb) {
        int kh = tap / 9, kw = tap - kh * 9;
        int sh = flip ? 8 - kh : kh, sw = flip ? 8 - kw : kw;
        int dh = m * (kh - 4), dw = m * (kw - 4);
        const char* abase = xb + (size_t)(sh * 9 + sw) * SAI_STRIDE
                          + (ptrdiff_t)(dh * 48 + dw) * 128;
        const uint32_t aoff = pb * 32768u;
        #pragma unroll
        for (int i = 0; i < 8; i++) {
            int oh2 = (int)((pack_oh >> (8 * i)) & 255) + dh;
            int ow2 = (int)((pack_ow >> (8 * i)) & 255) + dw;
            bool valid = ((unsigned)oh2 < 48u) & ((unsigned)ow2 < 48u);
            uint32_t sz = valid ? 16u : 0u;
            const char* src = valid ? (abase + FA[i]) : xb;
            asm volatile("cp.async.cg.shared.global [%0], [%1], 16, %2;"
                         :: "r"(dstA0 + aoff + (uint32_t)i * 4096u), "l"(src),
                            "r"(sz) : "memory");
        }
        const char* bsrc = wb + (ptrdiff_t)tap * 8192;
        const uint32_t boff = pb * 8192u;
        #pragma unroll
        for (int i = 0; i < 2; i++)
            asm volatile("cp.async.cg.shared.global [%0], [%1], 16;"
                         :: "r"(dstB0 + boff + (uint32_t)i * 4096u),
                            "l"(bsrc + (ptrdiff_t)i * 4096) : "memory");
        asm volatile("cp.async.commit_group;" ::: "memory");
    };

    stage(0, 0u);
    for (int tap = 0; tap < 81; tap++) {
        uint32_t buf = (uint32_t)(tap & 1);
        if (tap + 1 < 81) {
            stage(tap + 1, buf ^ 1u);
            asm volatile("cp.async.wait_group 1;" ::: "memory");
        } else {
            asm volatile("cp.async.wait_group 0;" ::: "memory");
        }
        __syncthreads();

        const uint32_t Ab = smA + buf * 32768u;
        const uint32_t Bb = smB + buf * 8192u;
        #pragma unroll
        for (int kc = 0; kc < 4; kc++) {
            uint32_t br[8][2];
            #pragma unroll
            for (int q = 0; q < 4; q++) {
                uint32_t r0, r1, r2, r3;
                asm volatile(
                    "ldmatrix.sync.aligned.m8n8.x4.trans.shared.b16 {%0,%1,%2,%3}, [%4];"
                    : "=r"(r0), "=r"(r1), "=r"(r2), "=r"(r3)
                    : "r"(Bb + adB0[q] + (uint32_t)kc * 2048u));
                br[2 * q][0] = r0; br[2 * q][1] = r1;
                br[2 * q + 1][0] = r2; br[2 * q + 1][1] = r3;
            }
            #pragma unroll
            for (int j = 0; j < 2; j++) {
                uint32_t a0, a1, a2, a3;
                asm volatile(
                    "ldmatrix.sync.aligned.m8n8.x4.shared.b16 {%0,%1,%2,%3}, [%4];"
                    : "=r"(a0), "=r"(a1), "=r"(a2), "=r"(a3)
                    : "r"(Ab + adA[j][kc]));
                #pragma unroll
                for (int nt = 0; nt < 8; nt++) {
                    asm volatile(
                        "mma.sync.aligned.m16n8k16.row.col.f32.f16.f16.f32 "
                        "{%0,%1,%2,%3},{%4,%5,%6,%7},{%8,%9},{%0,%1,%2,%3};"
                        : "+f"(acc[j][nt][0]), "+f"(acc[j][nt][1]),
                          "+f"(acc[j][nt][2]), "+f"(acc[j][nt][3])
                        : "r"(a0), "r"(a1), "r"(a2), "r"(a3),
                          "r"(br[nt][0]), "r"(br[nt][1]));
                }
            }
        }
        __syncthreads();
    }

    // ---- epilogue: scatter acc to g_conv[d][b][co][oh][ow] ----
    #pragma unroll
    for (int j = 0; j < 2; j++) {
        int r0 = 32 * w + 16 * j + (lane >> 2);
        #pragma unroll
        for (int hh = 0; hh < 2; hh++) {
            int s = tile * 256 + r0 + 8 * hh;
            int bb = s / 2304, rem = s % 2304;
            int oh = rem / 48, ow = rem % 48;
            float* p = g_conv + (((size_t)(dIdx * NB + bb) * NCO) * HW + oh) * HW + ow;
            #pragma unroll
            for (int nt = 0; nt < 8; nt++) {
                int co = nt * 8 + (lane & 3) * 2;
                p[(size_t)co * (HW * HW)]       = acc[j][nt][2 * hh];
                p[(size_t)(co + 1) * (HW * HW)] = acc[j][nt][2 * hh + 1];
            }
        }
    }
}

// ---------------------------------------------------------------------------
// Kernel E: assemble cost volume [B, CO, 68, 48, 48].
// ---------------------------------------------------------------------------
__global__ void assemble_kernel(float* __restrict__ out) {
    const int total = NB * NCO * 17 * HW * (HW / 4);
    int idx = blockIdx.x * 256 + threadIdx.x;
    if (idx >= total) return;
    int w4 = idx % 12; int t = idx / 12;
    int oh = t % 48;   t /= 48;
    int i  = t % 17;   t /= 17;
    int co = t % 64;   int b = t / 64;

    float4 val = make_float4(0.f, 0.f, 0.f, 0.f);
    if (i & 1) {
        int p = (i - 1) >> 1;
        const float* base1 = g_conv +
            (((size_t)(p * NB + b) * NCO + co) * HW + oh) * HW;
        const float* base2 = base1 + (size_t)NB * NCO * HW * HW;
        float4 a = ((const float4*)base1)[w4];
        float4 c = ((const float4*)base2)[w4];
        val = make_float4(0.5f * (a.x + c.x), 0.5f * (a.y + c.y),
                          0.5f * (a.z + c.z), 0.5f * (a.w + c.w));
    }
    float4* o = (float4*)(out +
        ((((size_t)b * NCO + co) * 68 + 4 * i) * HW + oh) * HW) + w4;
    o[0]    = val;
    o[576]  = val;
    o[1152] = val;
    o[1728] = val;
}

// ---------------------------------------------------------------------------
extern "C" void kernel_launch(void* const* d_in, const int* in_sizes, int n_in,
                              void* d_out, int out_size) {
    const float* x = (const float*)d_in[0];
    const float* w = (const float*)d_in[1];
    if (n_in >= 2 && in_sizes[0] < in_sizes[1]) {
        const float* tmp = x; x = w; w = tmp;
    }
    cudaFuncSetAttribute(conv_kernel,
                         cudaFuncAttributeMaxDynamicSharedMemorySize, CONV_SMEM);
    cudaFuncSetAttribute(reorg_kernel,
                         cudaFuncAttributeMaxDynamicSharedMemorySize, REORG_SMEM);
    reorg_kernel<<<dim3(432, NB), 256, REORG_SMEM>>>(x);
    wprep_kernel<<<(81 * NCI * NCO + 255) / 256, 256>>>(w);
    conv_kernel<<<dim3(ND, NTILES), 256, CONV_SMEM>>>();
    assemble_kernel<<<(NB * NCO * 17 * HW * (HW / 4) + 255) / 256, 256>>>((float*)d_out);
}

// round 17
// speedup vs baseline: 1.3897x; 1.3897x over previous
#include <cuda_runtime.h>
#include <cuda_fp16.h>
#include <cstdint>

#define HW   48
#define NB   4
#define NCI  64
#define NCO  64
#define ND   9
#define NTILES 72        // 9216 / 128
#define SAI_STRIDE (NB * 2304 * 128)     // bytes per sub-aperture image

// ---------------- device scratch (no allocation allowed) -------------------
// unpadded SAI tensor: [sai(81)][b(4)][oh(48)][ow(48)][ci(64)] fp16  (95.6 MB)
__device__ __half g_x[(size_t)81 * NB * HW * HW * NCI];
__device__ __half g_w[81 * NCI * NCO];                       // [tap][ci][co]
__device__ float  g_conv[(size_t)ND * NB * NCO * HW * HW];   // 21.2 MB

__device__ __forceinline__ uint32_t smem_u32(const void* p) {
    uint32_t a;
    asm("{ .reg .u64 t; cvta.to.shared.u64 t, %1; cvt.u32.u64 %0, t; }"
        : "=r"(a) : "l"(p));
    return a;
}

// ---------------------------------------------------------------------------
// Kernel B: reorg x[b][ci][432][432] -> SAI fp16 [sai][b][oh][ow][ci]
// (v1: measured best — do not touch.)
// ---------------------------------------------------------------------------
__global__ void __launch_bounds__(256) reorg_kernel(const float* __restrict__ x) {
    __shared__ float xs[16][433];
    const int ih = blockIdx.x, b = blockIdx.y;
    const int sh = ih % 9, ohm = ih / 9;
    for (int c0 = 0; c0 < NCI; c0 += 16) {
        if (c0) __syncthreads();
        for (int i = threadIdx.x; i < 16 * 432; i += 256) {
            int ci = i / 432, iw = i - ci * 432;
            xs[ci][iw] = x[((size_t)(b * NCI + c0 + ci) * 432 + ih) * 432 + iw];
        }
        __syncthreads();
        for (int i = threadIdx.x; i < 432 * 8; i += 256) {
            int cp = i & 7; int t2 = i >> 3;
            int owm = t2 % 48, sw = t2 / 48;
            __half h0 = __float2half(xs[2 * cp][owm * 9 + sw]);
            __half h1 = __float2half(xs[2 * cp + 1][owm * 9 + sw]);
            size_t o = (((size_t)(sh * 9 + sw) * NB + b) * (HW * HW)
                        + (size_t)ohm * HW + owm) * NCI + c0 + 2 * cp;
            *(__half2*)(g_x + o) = __halves2half2(h0, h1);
        }
    }
}

// ---------------------------------------------------------------------------
// Kernel C: weight prep  w[co][ci][kh][kw] -> g_w[tap][ci][co] fp16
// ---------------------------------------------------------------------------
__global__ void wprep_kernel(const float* __restrict__ w) {
    int idx = blockIdx.x * 256 + threadIdx.x;
    if (idx >= 81 * NCI * NCO) return;
    int co = idx & 63, ci = (idx >> 6) & 63, tap = idx >> 12;
    g_w[idx] = __float2half(w[(size_t)co * 5184 + ci * 81 + tap]);
}

// ---------------------------------------------------------------------------
// Kernel D: HMMA implicit-GEMM conv.  grid (9, 72), 256 thr (8 warps),
// 4 CTAs/SM (48KB smem, <=64 regs target).  CTA tile D[M=128][N=64]:
// 8 warps x (32x32) tiles — wr=w>>1 row-group, wc=w&1 co-half — exactly
// covers 128x64.  81 taps, K=64/tap; OOB via cp.async src_size=0.
// ---------------------------------------------------------------------------
#define CONV_SMEM (2 * 16384 + 2 * 8192)    // 49152 B
__global__ void __launch_bounds__(256, 4) conv_kernel() {
    extern __shared__ __align__(128) char dsm[];
    const uint32_t smA = smem_u32(dsm);
    const uint32_t smB = smA + 32768u;

    const int dIdx = blockIdx.x, tile = blockIdx.y;
    const int d = dIdx - 4;
    const int m = d < 0 ? -d : d;
    const bool flip = (d > 0);
    const int t = threadIdx.x, lane = t & 31, w = t >> 5;
    const int wr = w >> 1, wc = w & 1;

    // ---- staging: thread owns 4 A chunks (16B) + 2 B chunks, linear ----
    const uint32_t swz   = (uint32_t)(((t & 7) ^ ((t >> 3) & 7)) << 4);
    const uint32_t dstA0 = smA + (uint32_t)(t >> 3) * 128u + swz;
    const uint32_t dstB0 = smB + (uint32_t)(t >> 3) * 128u + swz;
    const int32_t  FA0   = (tile * 128 + (t >> 3)) * 128 + (t & 7) * 16;

    uint32_t pack_oh = 0, pack_ow = 0;      // 4 rows, 8 bits each
    #pragma unroll
    for (int i = 0; i < 4; i++) {
        int s = tile * 128 + (t >> 3) + 32 * i;
        pack_oh |= (uint32_t)((s / 48) % 48) << (8 * i);
        pack_ow |= (uint32_t)(s % 48) << (8 * i);
    }

    // ---- ldmatrix lane addressing: linear bases + shared swizzle tables ----
    // row&7 == lane&7 for all row bases (multiples of 8 added), so:
    uint32_t colswA[4], colswB[2];
    #pragma unroll
    for (int i = 0; i < 4; i++)
        colswA[i] = (uint32_t)(((i * 2 + (lane >> 4)) ^ (lane & 7)) << 4);
    #pragma unroll
    for (int q = 0; q < 2; q++)
        colswB[q] = (uint32_t)(((4 * wc + q * 2 + (lane >> 4)) ^ (lane & 7)) << 4);
    const uint32_t rowA = (uint32_t)((32 * wr + (lane & 15)) * 128);
    const uint32_t rowB = (uint32_t)((lane & 15) * 128);

    float acc[2][4][4];
    #pragma unroll
    for (int j = 0; j < 2; j++)
        #pragma unroll
        for (int nt = 0; nt < 4; nt++)
            #pragma unroll
            for (int k = 0; k < 4; k++) acc[j][nt][k] = 0.f;

    const char* xb = (const char*)g_x;
    const char* wb = (const char*)g_w + (size_t)t * 16;

    auto stage = [&](int tap, uint32_t pb) {
        int kh = tap / 9, kw = tap - kh * 9;
        int sh = flip ? 8 - kh : kh, sw = flip ? 8 - kw : kw;
        int dh = m * (kh - 4), dw = m * (kw - 4);
        const char* abase = xb + (size_t)(sh * 9 + sw) * SAI_STRIDE
                          + (ptrdiff_t)(dh * 48 + dw) * 128 + FA0;
        const uint32_t aoff = pb * 16384u;
        #pragma unroll
        for (int i = 0; i < 4; i++) {
            int oh2 = (int)((pack_oh >> (8 * i)) & 255) + dh;
            int ow2 = (int)((pack_ow >> (8 * i)) & 255) + dw;
            bool valid = ((unsigned)oh2 < 48u) & ((unsigned)ow2 < 48u);
            uint32_t sz = valid ? 16u : 0u;
            const char* src = valid ? (abase + (ptrdiff_t)i * 4096) : xb;
            asm volatile("cp.async.cg.shared.global [%0], [%1], 16, %2;"
                         :: "r"(dstA0 + aoff + (uint32_t)i * 4096u), "l"(src),
                            "r"(sz) : "memory");
        }
        const char* bsrc = wb + (ptrdiff_t)tap * 8192;
        const uint32_t boff = pb * 8192u;
        #pragma unroll
        for (int i = 0; i < 2; i++)
            asm volatile("cp.async.cg.shared.global [%0], [%1], 16;"
                         :: "r"(dstB0 + boff + (uint32_t)i * 4096u),
                            "l"(bsrc + (ptrdiff_t)i * 4096) : "memory");
        asm volatile("cp.async.commit_group;" ::: "memory");
    };

    stage(0, 0u);
    for (int tap = 0; tap < 81; tap++) {
        uint32_t buf = (uint32_t)(tap & 1);
        if (tap + 1 < 81) {
            stage(tap + 1, buf ^ 1u);
            asm volatile("cp.async.wait_group 1;" ::: "memory");
        } else {
            asm volatile("cp.async.wait_group 0;" ::: "memory");
        }
        __syncthreads();

        const uint32_t Ab = rowA + smA + buf * 16384u;
        const uint32_t Bb = rowB + smB + buf * 8192u;
        #pragma unroll
        for (int kc = 0; kc < 4; kc++) {
            uint32_t br[4][2];
            #pragma unroll
            for (int q = 0; q < 2; q++) {
                uint32_t r0, r1, r2, r3;
                asm volatile(
                    "ldmatrix.sync.aligned.m8n8.x4.trans.shared.b16 {%0,%1,%2,%3}, [%4];"
                    : "=r"(r0), "=r"(r1), "=r"(r2), "=r"(r3)
                    : "r"(Bb + colswB[q] + (uint32_t)kc * 2048u));
                br[2 * q][0] = r0; br[2 * q][1] = r1;
                br[2 * q + 1][0] = r2; br[2 * q + 1][1] = r3;
            }
            #pragma unroll
            for (int j = 0; j < 2; j++) {
                uint32_t a0, a1, a2, a3;
                asm volatile(
                    "ldmatrix.sync.aligned.m8n8.x4.shared.b16 {%0,%1,%2,%3}, [%4];"
                    : "=r"(a0), "=r"(a1), "=r"(a2), "=r"(a3)
                    : "r"(Ab + colswA[kc] + (uint32_t)j * 2048u));
                #pragma unroll
                for (int nt = 0; nt < 4; nt++) {
                    asm volatile(
                        "mma.sync.aligned.m16n8k16.row.col.f32.f16.f16.f32 "
                        "{%0,%1,%2,%3},{%4,%5,%6,%7},{%8,%9},{%0,%1,%2,%3};"
                        : "+f"(acc[j][nt][0]), "+f"(acc[j][nt][1]),
                          "+f"(acc[j][nt][2]), "+f"(acc[j][nt][3])
                        : "r"(a0), "r"(a1), "r"(a2), "r"(a3),
                          "r"(br[nt][0]), "r"(br[nt][1]));
                }
            }
        }
        __syncthreads();
    }

    // ---- epilogue: scatter acc to g_conv[d][b][co][oh][ow] ----
    #pragma unroll
    for (int j = 0; j < 2; j++) {
        int r0 = 32 * wr + 16 * j + (lane >> 2);
        #pragma unroll
        for (int hh = 0; hh < 2; hh++) {
            int s = tile * 128 + r0 + 8 * hh;
            int bb = s / 2304, rem = s % 2304;
            int oh = rem / 48, ow = rem % 48;
            float* p = g_conv + (((size_t)(dIdx * NB + bb) * NCO) * HW + oh) * HW + ow;
            #pragma unroll
            for (int nt = 0; nt < 4; nt++) {
                int co = 32 * wc + nt * 8 + (lane & 3) * 2;
                p[(size_t)co * (HW * HW)]       = acc[j][nt][2 * hh];
                p[(size_t)(co + 1) * (HW * HW)] = acc[j][nt][2 * hh + 1];
            }
        }
    }
}

// ---------------------------------------------------------------------------
// Kernel E: assemble cost volume [B, CO, 68, 48, 48].
// ---------------------------------------------------------------------------
__global__ void assemble_kernel(float* __restrict__ out) {
    const int total = NB * NCO * 17 * HW * (HW / 4);
    int idx = blockIdx.x * 256 + threadIdx.x;
    if (idx >= total) return;
    int w4 = idx % 12; int t = idx / 12;
    int oh = t % 48;   t /= 48;
    int i  = t % 17;   t /= 17;
    int co = t % 64;   int b = t / 64;

    float4 val = make_float4(0.f, 0.f, 0.f, 0.f);
    if (i & 1) {
        int p = (i - 1) >> 1;
        const float* base1 = g_conv +
            (((size_t)(p * NB + b) * NCO + co) * HW + oh) * HW;
        const float* base2 = base1 + (size_t)NB * NCO * HW * HW;
        float4 a = ((const float4*)base1)[w4];
        float4 c = ((const float4*)base2)[w4];
        val = make_float4(0.5f * (a.x + c.x), 0.5f * (a.y + c.y),
                          0.5f * (a.z + c.z), 0.5f * (a.w + c.w));
    }
    float4* o = (float4*)(out +
        ((((size_t)b * NCO + co) * 68 + 4 * i) * HW + oh) * HW) + w4;
    o[0]    = val;
    o[576]  = val;
    o[1152] = val;
    o[1728] = val;
}

// ---------------------------------------------------------------------------
extern "C" void kernel_launch(void* const* d_in, const int* in_sizes, int n_in,
                              void* d_out, int out_size) {
    const float* x = (const float*)d_in[0];
    const float* w = (const float*)d_in[1];
    if (n_in >= 2 && in_sizes[0] < in_sizes[1]) {
        const float* tmp = x; x = w; w = tmp;
    }
    cudaFuncSetAttribute(conv_kernel,
                         cudaFuncAttributeMaxDynamicSharedMemorySize, CONV_SMEM);
    reorg_kernel<<<dim3(432, NB), 256>>>(x);
    wprep_kernel<<<(81 * NCI * NCO + 255) / 256, 256>>>(w);
    conv_kernel<<<dim3(ND, NTILES), 256, CONV_SMEM>>>();
    assemble_kernel<<<(NB * NCO * 17 * HW * (HW / 4) + 255) / 256, 256>>>((float*)d_out);
}